// round 6
// baseline (speedup 1.0000x reference)
#include <cuda_runtime.h>
#include <stdint.h>

// Problem constants (fixed benchmark): N=1e6, IN_C=OUT_C=64, FEAT_C=128, G=4096
#define N_MAX 1000000
#define G_MAX 4096

// Scratch (static device allocations are allowed)
__device__ int   d_count[G_MAX];
__device__ int   d_offsets[G_MAX + 1];
__device__ int   d_cursor[G_MAX];
__device__ int   d_order[N_MAX];
__device__ float d_mu[G_MAX * 64];
__device__ float d_sig[G_MAX * 64];

// ---------------------------------------------------------------------------
// f32x2 packed helpers (sm_100+): FFMA2 is only reachable via PTX.
// ---------------------------------------------------------------------------
__device__ __forceinline__ unsigned long long pack2(float v) {
    unsigned long long r;
    asm("mov.b64 %0, {%1, %1};" : "=l"(r) : "f"(v));
    return r;
}
__device__ __forceinline__ unsigned long long packxy(float x, float y) {
    unsigned long long r;
    asm("mov.b64 %0, {%1, %2};" : "=l"(r) : "f"(x), "f"(y));
    return r;
}
__device__ __forceinline__ unsigned long long ffma2(unsigned long long a,
                                                    unsigned long long b,
                                                    unsigned long long c) {
    unsigned long long d;
    asm("fma.rn.f32x2 %0, %1, %2, %3;" : "=l"(d) : "l"(a), "l"(b), "l"(c));
    return d;
}
__device__ __forceinline__ float2 unpack2(unsigned long long v) {
    float2 f;
    asm("mov.b64 {%0, %1}, %2;" : "=f"(f.x), "=f"(f.y) : "l"(v));
    return f;
}

// ---------------------------------------------------------------------------
__global__ void init_kernel(int G) {
    int i = blockIdx.x * blockDim.x + threadIdx.x;
    if (i < G) d_count[i] = 0;
}

__global__ void hist_kernel(const int* __restrict__ seg, int n) {
    int i = blockIdx.x * blockDim.x + threadIdx.x;
    if (i < n) atomicAdd(&d_count[seg[i]], 1);
}

// Shuffle-based scan of up to 4096 counts (1024 threads x 4 each, 2 barriers)
__global__ void scan_kernel(int G) {
    __shared__ int wsum[32];
    __shared__ int wpre[32];
    const unsigned full = 0xffffffffu;
    int t = threadIdx.x, lane = t & 31, w = t >> 5;
    int v[4];
    int s = 0;
#pragma unroll
    for (int i = 0; i < 4; i++) {
        int g = 4 * t + i;
        v[i] = (g < G) ? d_count[g] : 0;
        s += v[i];
    }
    int sc = s;  // inclusive scan within warp
#pragma unroll
    for (int off = 1; off < 32; off <<= 1) {
        int o = __shfl_up_sync(full, sc, off);
        if (lane >= off) sc += o;
    }
    if (lane == 31) wsum[w] = sc;
    __syncthreads();
    if (w == 0) {
        int ws = wsum[lane];
        int p = ws;
#pragma unroll
        for (int off = 1; off < 32; off <<= 1) {
            int o = __shfl_up_sync(full, p, off);
            if (lane >= off) p += o;
        }
        wpre[lane] = p - ws;  // exclusive warp prefix
    }
    __syncthreads();
    int excl = wpre[w] + sc - s;  // exclusive prefix for this thread's 4 vals
#pragma unroll
    for (int i = 0; i < 4; i++) {
        int g = 4 * t + i;
        if (g < G) {
            d_offsets[g] = excl;
            d_cursor[g]  = excl;
            excl += v[i];
        }
    }
    if (t == 1023) d_offsets[G] = excl;
}

__global__ void scatter_kernel(const int* __restrict__ seg, int n) {
    int i = blockIdx.x * blockDim.x + threadIdx.x;
    if (i < n) {
        int p = atomicAdd(&d_cursor[seg[i]], 1);
        d_order[p] = i;
    }
}

// mu = origin_feat @ W_mu + b_mu ; sig = origin_feat @ W_sig + b_sig
__global__ void musig_kernel(const float* __restrict__ feat,
                             const float* __restrict__ Wmu, const float* __restrict__ bmu,
                             const float* __restrict__ Wsg, const float* __restrict__ bsg,
                             int G) {
    __shared__ float sF[4][128];
    int t  = threadIdx.x;
    int g0 = blockIdx.x * 4;
    for (int i = t; i < 512; i += 256) {
        int gl = i >> 7, k = i & 127;
        int g  = g0 + gl;
        sF[gl][k] = (g < G) ? feat[(size_t)g * 128 + k] : 0.f;
    }
    __syncthreads();
    int gl = t >> 6, c = t & 63;
    int g  = g0 + gl;
    if (g >= G) return;
    float am = bmu[c], as = bsg[c];
#pragma unroll 4
    for (int k = 0; k < 128; k++) {
        float f = sF[gl][k];
        am = fmaf(f, Wmu[k * 64 + c], am);
        as = fmaf(f, Wsg[k * 64 + c], as);
    }
    d_mu[(size_t)g * 64 + c]  = am;
    d_sig[(size_t)g * 64 + c] = as;
}

// ---------------------------------------------------------------------------
// Per-group fused kernel, f32x2 edition.
// Thread grid 32x8: tr = t>>3 (row block, 2 rows), tc = t&7 (col block, 8 cols
// as 4 f32x2 pairs). Chunk = 64 rows. h cached in SMEM (CAP rows), with the
// float4 rotation swizzle: float4 group f of row r lives at index (f + r%16)%16.
// ---------------------------------------------------------------------------
#define CAP 320
#define CHUNK 64

__device__ __forceinline__ void load_rows(const float* __restrict__ x,
                                          int off, int base, int cnt,
                                          int sr, int sq, float4 v[4]) {
    int gr = base + sr;
    if (gr < cnt) {
        int gi = __ldg(&d_order[off + gr]);
        const float4* xr = reinterpret_cast<const float4*>(x + (size_t)gi * 64);
#pragma unroll
        for (int i = 0; i < 4; i++) v[i] = xr[sq * 4 + i];
    } else {
#pragma unroll
        for (int i = 0; i < 4; i++) v[i] = make_float4(0.f, 0.f, 0.f, 0.f);
    }
}

__device__ __forceinline__ void sts_rows(float* __restrict__ sH, int slot,
                                         int sr, int sq, const float4 v[4]) {
    float4* row4 = reinterpret_cast<float4*>(sH + (size_t)(slot + sr) * 64);
    int rot = sr & 15;
#pragma unroll
    for (int i = 0; i < 4; i++) row4[(sq * 4 + i + rot) & 15] = v[i];
}

// GEMM on one 64-row chunk: 2 rows x 4 col-pairs per thread, FFMA2 inner loop.
__device__ __forceinline__ void chunk_gemm2(const float* __restrict__ sH,
                                            const float* __restrict__ sW,
                                            const unsigned long long bp[4],
                                            int slot, int tr, int tc,
                                            unsigned long long acc[2][4]) {
#pragma unroll
    for (int p = 0; p < 4; p++) { acc[0][p] = bp[p]; acc[1][p] = bp[p]; }
    int lr0 = tr * 2, lr1 = lr0 + 1;
    const float4* row0 = reinterpret_cast<const float4*>(sH + (size_t)(slot + lr0) * 64);
    const float4* row1 = reinterpret_cast<const float4*>(sH + (size_t)(slot + lr1) * 64);
    int rot0 = lr0 & 15, rot1 = lr1 & 15;
#pragma unroll 4
    for (int k4 = 0; k4 < 16; k4++) {
        float4 x0 = row0[(k4 + rot0) & 15];
        float4 x1 = row1[(k4 + rot1) & 15];
#pragma unroll
        for (int kk = 0; kk < 4; kk++) {
            int k = k4 * 4 + kk;
            const ulonglong2* wrow = reinterpret_cast<const ulonglong2*>(sW + k * 64);
            ulonglong2 wA = wrow[tc * 2];      // cols 8tc..8tc+3 as 2 pairs
            ulonglong2 wB = wrow[tc * 2 + 1];  // cols 8tc+4..8tc+7
            float xe0 = (kk == 0) ? x0.x : (kk == 1) ? x0.y : (kk == 2) ? x0.z : x0.w;
            float xe1 = (kk == 0) ? x1.x : (kk == 1) ? x1.y : (kk == 2) ? x1.z : x1.w;
            unsigned long long p0 = pack2(xe0);
            unsigned long long p1 = pack2(xe1);
            acc[0][0] = ffma2(p0, wA.x, acc[0][0]);
            acc[0][1] = ffma2(p0, wA.y, acc[0][1]);
            acc[0][2] = ffma2(p0, wB.x, acc[0][2]);
            acc[0][3] = ffma2(p0, wB.y, acc[0][3]);
            acc[1][0] = ffma2(p1, wA.x, acc[1][0]);
            acc[1][1] = ffma2(p1, wA.y, acc[1][1]);
            acc[1][2] = ffma2(p1, wB.x, acc[1][2]);
            acc[1][3] = ffma2(p1, wB.y, acc[1][3]);
        }
    }
}

__global__ __launch_bounds__(256, 2) void group_kernel(const float* __restrict__ x,
                                                       const float* __restrict__ Wfc,
                                                       const float* __restrict__ bfc,
                                                       float* __restrict__ out) {
    extern __shared__ float sm[];
    float* sW     = sm;                 // 4096
    float* sH     = sm + 4096;          // CAP*64
    float* sSum   = sH + CAP * 64;      // 64
    float* sSq    = sSum + 64;          // 64
    float* sMu    = sSq + 64;           // 64
    float* sSig   = sMu + 64;           // 64
    float* sScale = sSig + 64;          // 64
    float* sShift = sScale + 64;        // 64

    int t   = threadIdx.x;
    int g   = blockIdx.x;
    int off = d_offsets[g];
    int cnt = d_offsets[g + 1] - off;

    for (int i = t; i < 4096; i += 256) sW[i] = Wfc[i];
    if (t < 64) {
        sMu[t]  = d_mu[(size_t)g * 64 + t];
        sSig[t] = d_sig[(size_t)g * 64 + t];
        sSum[t] = 0.f;
        sSq[t]  = 0.f;
    }
    int tr = t >> 3, tc = t & 7;
    unsigned long long bp[4];
    {
        float4 ba = reinterpret_cast<const float4*>(bfc)[tc * 2];
        float4 bb = reinterpret_cast<const float4*>(bfc)[tc * 2 + 1];
        bp[0] = packxy(ba.x, ba.y);
        bp[1] = packxy(ba.z, ba.w);
        bp[2] = packxy(bb.x, bb.y);
        bp[3] = packxy(bb.z, bb.w);
    }
    __syncthreads();
    if (cnt == 0) return;

    bool cached = (cnt <= CAP);
    int  nch    = (cnt + CHUNK - 1) >> 6;
    int  sr = t >> 2, sq = t & 3;  // staging: row, quarter
    int  lr0 = tr * 2, lr1 = lr0 + 1;

    float csum[8], csq[8];
#pragma unroll
    for (int j = 0; j < 8; j++) { csum[j] = 0.f; csq[j] = 0.f; }
    unsigned long long acc[2][4];

    if (cached) {
        // -------- pass 1, pipelined: prefetch LDG -> GEMM -> STS next --------
        float4 pv[4];
        load_rows(x, off, 0, cnt, sr, sq, pv);
        sts_rows(sH, 0, sr, sq, pv);
        __syncthreads();
        for (int c = 0; c < nch; c++) {
            int base = c << 6;
            bool havnext = (c + 1 < nch);
            if (havnext) load_rows(x, off, base + 64, cnt, sr, sq, pv);  // LDG under GEMM
            chunk_gemm2(sH, sW, bp, base, tr, tc, acc);
            float2 u[2][4];
#pragma unroll
            for (int r = 0; r < 2; r++)
#pragma unroll
                for (int p = 0; p < 4; p++) u[r][p] = unpack2(acc[r][p]);
            if (base + lr0 < cnt) {
#pragma unroll
                for (int p = 0; p < 4; p++) {
                    csum[2 * p]     += u[0][p].x;
                    csum[2 * p + 1] += u[0][p].y;
                    csq[2 * p]       = fmaf(u[0][p].x, u[0][p].x, csq[2 * p]);
                    csq[2 * p + 1]   = fmaf(u[0][p].y, u[0][p].y, csq[2 * p + 1]);
                }
            }
            if (base + lr1 < cnt) {
#pragma unroll
                for (int p = 0; p < 4; p++) {
                    csum[2 * p]     += u[1][p].x;
                    csum[2 * p + 1] += u[1][p].y;
                    csq[2 * p]       = fmaf(u[1][p].x, u[1][p].x, csq[2 * p]);
                    csq[2 * p + 1]   = fmaf(u[1][p].y, u[1][p].y, csq[2 * p + 1]);
                }
            }
            __syncwarp();  // x rows of this tr are only read within this warp
            {
                float4* r0 = reinterpret_cast<float4*>(sH + (size_t)(base + lr0) * 64);
                float4* r1 = reinterpret_cast<float4*>(sH + (size_t)(base + lr1) * 64);
                int ro0 = lr0 & 15, ro1 = lr1 & 15;
                r0[(tc * 2 + ro0) & 15]     = make_float4(u[0][0].x, u[0][0].y, u[0][1].x, u[0][1].y);
                r0[(tc * 2 + 1 + ro0) & 15] = make_float4(u[0][2].x, u[0][2].y, u[0][3].x, u[0][3].y);
                r1[(tc * 2 + ro1) & 15]     = make_float4(u[1][0].x, u[1][0].y, u[1][1].x, u[1][1].y);
                r1[(tc * 2 + 1 + ro1) & 15] = make_float4(u[1][2].x, u[1][2].y, u[1][3].x, u[1][3].y);
            }
            if (havnext) sts_rows(sH, base + 64, sr, sq, pv);
            __syncthreads();
        }
    } else {
        // -------- rare big-group path: plain staged GEMM, no caching --------
        float4 pv[4];
        for (int c = 0; c < nch; c++) {
            int base = c << 6;
            load_rows(x, off, base, cnt, sr, sq, pv);
            sts_rows(sH, 0, sr, sq, pv);
            __syncthreads();
            chunk_gemm2(sH, sW, bp, 0, tr, tc, acc);
#pragma unroll
            for (int r = 0; r < 2; r++) {
                if (base + lr0 + r < cnt) {
#pragma unroll
                    for (int p = 0; p < 4; p++) {
                        float2 u = unpack2(acc[r][p]);
                        csum[2 * p]     += u.x;
                        csum[2 * p + 1] += u.y;
                        csq[2 * p]       = fmaf(u.x, u.x, csq[2 * p]);
                        csq[2 * p + 1]   = fmaf(u.y, u.y, csq[2 * p + 1]);
                    }
                }
            }
            __syncthreads();
        }
    }

    // -------- reduce stats: lanes {l, l+8, l+16, l+24} share cols --------
    const unsigned full = 0xffffffffu;
#pragma unroll
    for (int j = 0; j < 8; j++) {
        csum[j] += __shfl_down_sync(full, csum[j], 16);
        csum[j] += __shfl_down_sync(full, csum[j], 8);
        csq[j]  += __shfl_down_sync(full, csq[j], 16);
        csq[j]  += __shfl_down_sync(full, csq[j], 8);
    }
    if ((t & 31) < 8) {
#pragma unroll
        for (int j = 0; j < 8; j++) {
            atomicAdd(&sSum[tc * 8 + j], csum[j]);
            atomicAdd(&sSq[tc * 8 + j], csq[j]);
        }
    }
    __syncthreads();

    if (t < 64) {
        float inv_n = 1.0f / (float)cnt;
        float mean  = sSum[t] * inv_n;
        float var   = sSq[t] * inv_n - mean * mean;
        var = fmaxf(var, 0.f);
        float sc = sSig[t] * rsqrtf(var + 1e-14f);
        sScale[t] = sc;
        sShift[t] = sMu[t] - mean * sc;
    }
    __syncthreads();

    // -------- pass 2: apply + write --------
    if (cached) {
        int w = t >> 5, l = t & 31;
        float2 sc2 = reinterpret_cast<float2*>(sScale)[l];
        float2 sh2 = reinterpret_cast<float2*>(sShift)[l];
        for (int j = w; j < cnt; j += 8) {
            int gi  = __ldg(&d_order[off + j]);
            int col = (2 * l + 4 * (j & 15)) & 63;
            float2 h2 = *reinterpret_cast<float2*>(&sH[(size_t)j * 64 + col]);
            float2 o;
            o.x = fmaxf(fmaf(h2.x, sc2.x, sh2.x), 0.f);
            o.y = fmaxf(fmaf(h2.y, sc2.y, sh2.y), 0.f);
            reinterpret_cast<float2*>(out + (size_t)gi * 64)[l] = o;
        }
    } else {
        // recompute h per chunk and write directly
        float4 pv[4];
        float4 scA = reinterpret_cast<float4*>(sScale)[tc * 2];
        float4 scB = reinterpret_cast<float4*>(sScale)[tc * 2 + 1];
        float4 shA = reinterpret_cast<float4*>(sShift)[tc * 2];
        float4 shB = reinterpret_cast<float4*>(sShift)[tc * 2 + 1];
        int nch2 = (cnt + CHUNK - 1) >> 6;
        for (int c = 0; c < nch2; c++) {
            int base = c << 6;
            load_rows(x, off, base, cnt, sr, sq, pv);
            sts_rows(sH, 0, sr, sq, pv);
            __syncthreads();
            chunk_gemm2(sH, sW, bp, 0, tr, tc, acc);
#pragma unroll
            for (int r = 0; r < 2; r++) {
                int gr = base + tr * 2 + r;
                if (gr < cnt) {
                    int gi = __ldg(&d_order[off + gr]);
                    float2 u0 = unpack2(acc[r][0]);
                    float2 u1 = unpack2(acc[r][1]);
                    float2 u2 = unpack2(acc[r][2]);
                    float2 u3 = unpack2(acc[r][3]);
                    float4 oA, oB;
                    oA.x = fmaxf(fmaf(u0.x, scA.x, shA.x), 0.f);
                    oA.y = fmaxf(fmaf(u0.y, scA.y, shA.y), 0.f);
                    oA.z = fmaxf(fmaf(u1.x, scA.z, shA.z), 0.f);
                    oA.w = fmaxf(fmaf(u1.y, scA.w, shA.w), 0.f);
                    oB.x = fmaxf(fmaf(u2.x, scB.x, shB.x), 0.f);
                    oB.y = fmaxf(fmaf(u2.y, scB.y, shB.y), 0.f);
                    oB.z = fmaxf(fmaf(u3.x, scB.z, shB.z), 0.f);
                    oB.w = fmaxf(fmaf(u3.y, scB.w, shB.w), 0.f);
                    reinterpret_cast<float4*>(out + (size_t)gi * 64)[tc * 2]     = oA;
                    reinterpret_cast<float4*>(out + (size_t)gi * 64)[tc * 2 + 1] = oB;
                }
            }
            __syncthreads();
        }
    }
}

// ---------------------------------------------------------------------------
extern "C" void kernel_launch(void* const* d_in, const int* in_sizes, int n_in,
                              void* d_out, int out_size) {
    int wi = (n_in >= 10) ? 4 : 3;
    const float* x    = (const float*)d_in[0];
    const float* feat = (const float*)d_in[1];
    const int*   seg  = (const int*)d_in[2];
    const float* Wfc  = (const float*)d_in[wi + 0];
    const float* bfc  = (const float*)d_in[wi + 1];
    const float* Wmu  = (const float*)d_in[wi + 2];
    const float* bmu  = (const float*)d_in[wi + 3];
    const float* Wsg  = (const float*)d_in[wi + 4];
    const float* bsg  = (const float*)d_in[wi + 5];
    float* out = (float*)d_out;

    int n = in_sizes[0] / 64;
    int G = in_sizes[1] / 128;

    const size_t smem = (size_t)(4096 + CAP * 64 + 6 * 64) * sizeof(float); // 99840 B
    cudaFuncSetAttribute(group_kernel, cudaFuncAttributeMaxDynamicSharedMemorySize,
                         (int)smem);

    init_kernel<<<(G + 255) / 256, 256>>>(G);
    musig_kernel<<<(G + 3) / 4, 256>>>(feat, Wmu, bmu, Wsg, bsg, G);
    hist_kernel<<<(n + 255) / 256, 256>>>(seg, n);
    scan_kernel<<<1, 1024>>>(G);
    scatter_kernel<<<(n + 255) / 256, 256>>>(seg, n);
    group_kernel<<<G, 256, smem>>>(x, Wfc, bfc, out);
}

// round 7
// speedup vs baseline: 1.0030x; 1.0030x over previous
#include <cuda_runtime.h>
#include <stdint.h>

// Problem constants (fixed benchmark): N=1e6, IN_C=OUT_C=64, FEAT_C=128, G=4096
#define N_MAX 1000000
#define G_MAX 4096

// Scratch (static device allocations are allowed)
__device__ int   d_count[G_MAX];
__device__ int   d_offsets[G_MAX + 1];
__device__ int   d_cursor[G_MAX];
__device__ int   d_order[N_MAX];
__device__ float d_mu[G_MAX * 64];
__device__ float d_sig[G_MAX * 64];

// ---------------------------------------------------------------------------
// f32x2 packed helpers (sm_100+): FFMA2 is only reachable via PTX.
// ---------------------------------------------------------------------------
__device__ __forceinline__ unsigned long long pack2(float v) {
    unsigned long long r;
    asm("mov.b64 %0, {%1, %1};" : "=l"(r) : "f"(v));
    return r;
}
__device__ __forceinline__ unsigned long long packxy(float x, float y) {
    unsigned long long r;
    asm("mov.b64 %0, {%1, %2};" : "=l"(r) : "f"(x), "f"(y));
    return r;
}
__device__ __forceinline__ unsigned long long ffma2(unsigned long long a,
                                                    unsigned long long b,
                                                    unsigned long long c) {
    unsigned long long d;
    asm("fma.rn.f32x2 %0, %1, %2, %3;" : "=l"(d) : "l"(a), "l"(b), "l"(c));
    return d;
}
__device__ __forceinline__ float2 unpack2(unsigned long long v) {
    float2 f;
    asm("mov.b64 {%0, %1}, %2;" : "=f"(f.x), "=f"(f.y) : "l"(v));
    return f;
}

// ---------------------------------------------------------------------------
__global__ void init_kernel(int G) {
    int i = blockIdx.x * blockDim.x + threadIdx.x;
    if (i < G) d_count[i] = 0;
}

__global__ void hist_kernel(const int* __restrict__ seg, int n) {
    int i = blockIdx.x * blockDim.x + threadIdx.x;
    if (i < n) atomicAdd(&d_count[seg[i]], 1);
}

// Shuffle-based scan of up to 4096 counts (1024 threads x 4 each, 2 barriers)
__global__ void scan_kernel(int G) {
    __shared__ int wsum[32];
    __shared__ int wpre[32];
    const unsigned full = 0xffffffffu;
    int t = threadIdx.x, lane = t & 31, w = t >> 5;
    int v[4];
    int s = 0;
#pragma unroll
    for (int i = 0; i < 4; i++) {
        int g = 4 * t + i;
        v[i] = (g < G) ? d_count[g] : 0;
        s += v[i];
    }
    int sc = s;  // inclusive scan within warp
#pragma unroll
    for (int off = 1; off < 32; off <<= 1) {
        int o = __shfl_up_sync(full, sc, off);
        if (lane >= off) sc += o;
    }
    if (lane == 31) wsum[w] = sc;
    __syncthreads();
    if (w == 0) {
        int ws = wsum[lane];
        int p = ws;
#pragma unroll
        for (int off = 1; off < 32; off <<= 1) {
            int o = __shfl_up_sync(full, p, off);
            if (lane >= off) p += o;
        }
        wpre[lane] = p - ws;  // exclusive warp prefix
    }
    __syncthreads();
    int excl = wpre[w] + sc - s;  // exclusive prefix for this thread's 4 vals
#pragma unroll
    for (int i = 0; i < 4; i++) {
        int g = 4 * t + i;
        if (g < G) {
            d_offsets[g] = excl;
            d_cursor[g]  = excl;
            excl += v[i];
        }
    }
    if (t == 1023) d_offsets[G] = excl;
}

__global__ void scatter_kernel(const int* __restrict__ seg, int n) {
    int i = blockIdx.x * blockDim.x + threadIdx.x;
    if (i < n) {
        int p = atomicAdd(&d_cursor[seg[i]], 1);
        d_order[p] = i;
    }
}

// mu = origin_feat @ W_mu + b_mu ; sig = origin_feat @ W_sig + b_sig
__global__ void musig_kernel(const float* __restrict__ feat,
                             const float* __restrict__ Wmu, const float* __restrict__ bmu,
                             const float* __restrict__ Wsg, const float* __restrict__ bsg,
                             int G) {
    __shared__ float sF[4][128];
    int t  = threadIdx.x;
    int g0 = blockIdx.x * 4;
    for (int i = t; i < 512; i += 256) {
        int gl = i >> 7, k = i & 127;
        int g  = g0 + gl;
        sF[gl][k] = (g < G) ? feat[(size_t)g * 128 + k] : 0.f;
    }
    __syncthreads();
    int gl = t >> 6, c = t & 63;
    int g  = g0 + gl;
    if (g >= G) return;
    float am = bmu[c], as = bsg[c];
#pragma unroll 4
    for (int k = 0; k < 128; k++) {
        float f = sF[gl][k];
        am = fmaf(f, Wmu[k * 64 + c], am);
        as = fmaf(f, Wsg[k * 64 + c], as);
    }
    d_mu[(size_t)g * 64 + c]  = am;
    d_sig[(size_t)g * 64 + c] = as;
}

// ---------------------------------------------------------------------------
// Per-group fused kernel, f32x2 edition.
// Thread grid 32x8: tr = t>>3 (row block, 2 rows), tc = t&7 (col block, 8 cols
// as 4 f32x2 pairs). Chunk = 64 rows. h cached in SMEM (CAP rows), with the
// float4 rotation swizzle: float4 group f of row r lives at index (f + r%16)%16.
// ---------------------------------------------------------------------------
#define CAP 320
#define CHUNK 64

__device__ __forceinline__ void load_rows(const float* __restrict__ x,
                                          int off, int base, int cnt,
                                          int sr, int sq, float4 v[4]) {
    int gr = base + sr;
    if (gr < cnt) {
        int gi = __ldg(&d_order[off + gr]);
        const float4* xr = reinterpret_cast<const float4*>(x + (size_t)gi * 64);
#pragma unroll
        for (int i = 0; i < 4; i++) v[i] = xr[sq * 4 + i];
    } else {
#pragma unroll
        for (int i = 0; i < 4; i++) v[i] = make_float4(0.f, 0.f, 0.f, 0.f);
    }
}

__device__ __forceinline__ void sts_rows(float* __restrict__ sH, int slot,
                                         int sr, int sq, const float4 v[4]) {
    float4* row4 = reinterpret_cast<float4*>(sH + (size_t)(slot + sr) * 64);
    int rot = sr & 15;
#pragma unroll
    for (int i = 0; i < 4; i++) row4[(sq * 4 + i + rot) & 15] = v[i];
}

// GEMM on one 64-row chunk: 2 rows x 4 col-pairs per thread, FFMA2 inner loop.
__device__ __forceinline__ void chunk_gemm2(const float* __restrict__ sH,
                                            const float* __restrict__ sW,
                                            const unsigned long long bp[4],
                                            int slot, int tr, int tc,
                                            unsigned long long acc[2][4]) {
#pragma unroll
    for (int p = 0; p < 4; p++) { acc[0][p] = bp[p]; acc[1][p] = bp[p]; }
    int lr0 = tr * 2, lr1 = lr0 + 1;
    const float4* row0 = reinterpret_cast<const float4*>(sH + (size_t)(slot + lr0) * 64);
    const float4* row1 = reinterpret_cast<const float4*>(sH + (size_t)(slot + lr1) * 64);
    int rot0 = lr0 & 15, rot1 = lr1 & 15;
#pragma unroll 4
    for (int k4 = 0; k4 < 16; k4++) {
        float4 x0 = row0[(k4 + rot0) & 15];
        float4 x1 = row1[(k4 + rot1) & 15];
#pragma unroll
        for (int kk = 0; kk < 4; kk++) {
            int k = k4 * 4 + kk;
            const ulonglong2* wrow = reinterpret_cast<const ulonglong2*>(sW + k * 64);
            ulonglong2 wA = wrow[tc * 2];      // cols 8tc..8tc+3 as 2 pairs
            ulonglong2 wB = wrow[tc * 2 + 1];  // cols 8tc+4..8tc+7
            float xe0 = (kk == 0) ? x0.x : (kk == 1) ? x0.y : (kk == 2) ? x0.z : x0.w;
            float xe1 = (kk == 0) ? x1.x : (kk == 1) ? x1.y : (kk == 2) ? x1.z : x1.w;
            unsigned long long p0 = pack2(xe0);
            unsigned long long p1 = pack2(xe1);
            acc[0][0] = ffma2(p0, wA.x, acc[0][0]);
            acc[0][1] = ffma2(p0, wA.y, acc[0][1]);
            acc[0][2] = ffma2(p0, wB.x, acc[0][2]);
            acc[0][3] = ffma2(p0, wB.y, acc[0][3]);
            acc[1][0] = ffma2(p1, wA.x, acc[1][0]);
            acc[1][1] = ffma2(p1, wA.y, acc[1][1]);
            acc[1][2] = ffma2(p1, wB.x, acc[1][2]);
            acc[1][3] = ffma2(p1, wB.y, acc[1][3]);
        }
    }
}

__global__ __launch_bounds__(256, 2) void group_kernel(const float* __restrict__ x,
                                                       const float* __restrict__ Wfc,
                                                       const float* __restrict__ bfc,
                                                       float* __restrict__ out) {
    extern __shared__ float sm[];
    float* sW     = sm;                 // 4096
    float* sH     = sm + 4096;          // CAP*64
    float* sSum   = sH + CAP * 64;      // 64
    float* sSq    = sSum + 64;          // 64
    float* sMu    = sSq + 64;           // 64
    float* sSig   = sMu + 64;           // 64
    float* sScale = sSig + 64;          // 64
    float* sShift = sScale + 64;        // 64

    int t   = threadIdx.x;
    int g   = blockIdx.x;
    int off = d_offsets[g];
    int cnt = d_offsets[g + 1] - off;

    for (int i = t; i < 4096; i += 256) sW[i] = Wfc[i];
    if (t < 64) {
        sMu[t]  = d_mu[(size_t)g * 64 + t];
        sSig[t] = d_sig[(size_t)g * 64 + t];
        sSum[t] = 0.f;
        sSq[t]  = 0.f;
    }
    int tr = t >> 3, tc = t & 7;
    unsigned long long bp[4];
    {
        float4 ba = reinterpret_cast<const float4*>(bfc)[tc * 2];
        float4 bb = reinterpret_cast<const float4*>(bfc)[tc * 2 + 1];
        bp[0] = packxy(ba.x, ba.y);
        bp[1] = packxy(ba.z, ba.w);
        bp[2] = packxy(bb.x, bb.y);
        bp[3] = packxy(bb.z, bb.w);
    }
    __syncthreads();
    if (cnt == 0) return;

    bool cached = (cnt <= CAP);
    int  nch    = (cnt + CHUNK - 1) >> 6;
    int  sr = t >> 2, sq = t & 3;  // staging: row, quarter
    int  lr0 = tr * 2, lr1 = lr0 + 1;

    float csum[8], csq[8];
#pragma unroll
    for (int j = 0; j < 8; j++) { csum[j] = 0.f; csq[j] = 0.f; }
    unsigned long long acc[2][4];

    if (cached) {
        // -------- pass 1, pipelined: prefetch LDG -> GEMM -> STS next --------
        float4 pv[4];
        load_rows(x, off, 0, cnt, sr, sq, pv);
        sts_rows(sH, 0, sr, sq, pv);
        __syncthreads();
        for (int c = 0; c < nch; c++) {
            int base = c << 6;
            bool havnext = (c + 1 < nch);
            if (havnext) load_rows(x, off, base + 64, cnt, sr, sq, pv);  // LDG under GEMM
            chunk_gemm2(sH, sW, bp, base, tr, tc, acc);
            float2 u[2][4];
#pragma unroll
            for (int r = 0; r < 2; r++)
#pragma unroll
                for (int p = 0; p < 4; p++) u[r][p] = unpack2(acc[r][p]);
            if (base + lr0 < cnt) {
#pragma unroll
                for (int p = 0; p < 4; p++) {
                    csum[2 * p]     += u[0][p].x;
                    csum[2 * p + 1] += u[0][p].y;
                    csq[2 * p]       = fmaf(u[0][p].x, u[0][p].x, csq[2 * p]);
                    csq[2 * p + 1]   = fmaf(u[0][p].y, u[0][p].y, csq[2 * p + 1]);
                }
            }
            if (base + lr1 < cnt) {
#pragma unroll
                for (int p = 0; p < 4; p++) {
                    csum[2 * p]     += u[1][p].x;
                    csum[2 * p + 1] += u[1][p].y;
                    csq[2 * p]       = fmaf(u[1][p].x, u[1][p].x, csq[2 * p]);
                    csq[2 * p + 1]   = fmaf(u[1][p].y, u[1][p].y, csq[2 * p + 1]);
                }
            }
            __syncwarp();  // x rows of this tr are only read within this warp
            {
                float4* r0 = reinterpret_cast<float4*>(sH + (size_t)(base + lr0) * 64);
                float4* r1 = reinterpret_cast<float4*>(sH + (size_t)(base + lr1) * 64);
                int ro0 = lr0 & 15, ro1 = lr1 & 15;
                r0[(tc * 2 + ro0) & 15]     = make_float4(u[0][0].x, u[0][0].y, u[0][1].x, u[0][1].y);
                r0[(tc * 2 + 1 + ro0) & 15] = make_float4(u[0][2].x, u[0][2].y, u[0][3].x, u[0][3].y);
                r1[(tc * 2 + ro1) & 15]     = make_float4(u[1][0].x, u[1][0].y, u[1][1].x, u[1][1].y);
                r1[(tc * 2 + 1 + ro1) & 15] = make_float4(u[1][2].x, u[1][2].y, u[1][3].x, u[1][3].y);
            }
            if (havnext) sts_rows(sH, base + 64, sr, sq, pv);
            __syncthreads();
        }
    } else {
        // -------- rare big-group path: plain staged GEMM, no caching --------
        float4 pv[4];
        for (int c = 0; c < nch; c++) {
            int base = c << 6;
            load_rows(x, off, base, cnt, sr, sq, pv);
            sts_rows(sH, 0, sr, sq, pv);
            __syncthreads();
            chunk_gemm2(sH, sW, bp, 0, tr, tc, acc);
#pragma unroll
            for (int r = 0; r < 2; r++) {
                if (base + lr0 + r < cnt) {
#pragma unroll
                    for (int p = 0; p < 4; p++) {
                        float2 u = unpack2(acc[r][p]);
                        csum[2 * p]     += u.x;
                        csum[2 * p + 1] += u.y;
                        csq[2 * p]       = fmaf(u.x, u.x, csq[2 * p]);
                        csq[2 * p + 1]   = fmaf(u.y, u.y, csq[2 * p + 1]);
                    }
                }
            }
            __syncthreads();
        }
    }

    // -------- reduce stats: lanes {l, l+8, l+16, l+24} share cols --------
    const unsigned full = 0xffffffffu;
#pragma unroll
    for (int j = 0; j < 8; j++) {
        csum[j] += __shfl_down_sync(full, csum[j], 16);
        csum[j] += __shfl_down_sync(full, csum[j], 8);
        csq[j]  += __shfl_down_sync(full, csq[j], 16);
        csq[j]  += __shfl_down_sync(full, csq[j], 8);
    }
    if ((t & 31) < 8) {
#pragma unroll
        for (int j = 0; j < 8; j++) {
            atomicAdd(&sSum[tc * 8 + j], csum[j]);
            atomicAdd(&sSq[tc * 8 + j], csq[j]);
        }
    }
    __syncthreads();

    if (t < 64) {
        float inv_n = 1.0f / (float)cnt;
        float mean  = sSum[t] * inv_n;
        float var   = sSq[t] * inv_n - mean * mean;
        var = fmaxf(var, 0.f);
        float sc = sSig[t] * rsqrtf(var + 1e-14f);
        sScale[t] = sc;
        sShift[t] = sMu[t] - mean * sc;
    }
    __syncthreads();

    // -------- pass 2: apply + write --------
    if (cached) {
        int w = t >> 5, l = t & 31;
        float2 sc2 = reinterpret_cast<float2*>(sScale)[l];
        float2 sh2 = reinterpret_cast<float2*>(sShift)[l];
        for (int j = w; j < cnt; j += 8) {
            int gi  = __ldg(&d_order[off + j]);
            int col = (2 * l + 4 * (j & 15)) & 63;
            float2 h2 = *reinterpret_cast<float2*>(&sH[(size_t)j * 64 + col]);
            float2 o;
            o.x = fmaxf(fmaf(h2.x, sc2.x, sh2.x), 0.f);
            o.y = fmaxf(fmaf(h2.y, sc2.y, sh2.y), 0.f);
            reinterpret_cast<float2*>(out + (size_t)gi * 64)[l] = o;
        }
    } else {
        // recompute h per chunk and write directly
        float4 pv[4];
        float4 scA = reinterpret_cast<float4*>(sScale)[tc * 2];
        float4 scB = reinterpret_cast<float4*>(sScale)[tc * 2 + 1];
        float4 shA = reinterpret_cast<float4*>(sShift)[tc * 2];
        float4 shB = reinterpret_cast<float4*>(sShift)[tc * 2 + 1];
        int nch2 = (cnt + CHUNK - 1) >> 6;
        for (int c = 0; c < nch2; c++) {
            int base = c << 6;
            load_rows(x, off, base, cnt, sr, sq, pv);
            sts_rows(sH, 0, sr, sq, pv);
            __syncthreads();
            chunk_gemm2(sH, sW, bp, 0, tr, tc, acc);
#pragma unroll
            for (int r = 0; r < 2; r++) {
                int gr = base + tr * 2 + r;
                if (gr < cnt) {
                    int gi = __ldg(&d_order[off + gr]);
                    float2 u0 = unpack2(acc[r][0]);
                    float2 u1 = unpack2(acc[r][1]);
                    float2 u2 = unpack2(acc[r][2]);
                    float2 u3 = unpack2(acc[r][3]);
                    float4 oA, oB;
                    oA.x = fmaxf(fmaf(u0.x, scA.x, shA.x), 0.f);
                    oA.y = fmaxf(fmaf(u0.y, scA.y, shA.y), 0.f);
                    oA.z = fmaxf(fmaf(u1.x, scA.z, shA.z), 0.f);
                    oA.w = fmaxf(fmaf(u1.y, scA.w, shA.w), 0.f);
                    oB.x = fmaxf(fmaf(u2.x, scB.x, shB.x), 0.f);
                    oB.y = fmaxf(fmaf(u2.y, scB.y, shB.y), 0.f);
                    oB.z = fmaxf(fmaf(u3.x, scB.z, shB.z), 0.f);
                    oB.w = fmaxf(fmaf(u3.y, scB.w, shB.w), 0.f);
                    reinterpret_cast<float4*>(out + (size_t)gi * 64)[tc * 2]     = oA;
                    reinterpret_cast<float4*>(out + (size_t)gi * 64)[tc * 2 + 1] = oB;
                }
            }
            __syncthreads();
        }
    }
}

// ---------------------------------------------------------------------------
extern "C" void kernel_launch(void* const* d_in, const int* in_sizes, int n_in,
                              void* d_out, int out_size) {
    int wi = (n_in >= 10) ? 4 : 3;
    const float* x    = (const float*)d_in[0];
    const float* feat = (const float*)d_in[1];
    const int*   seg  = (const int*)d_in[2];
    const float* Wfc  = (const float*)d_in[wi + 0];
    const float* bfc  = (const float*)d_in[wi + 1];
    const float* Wmu  = (const float*)d_in[wi + 2];
    const float* bmu  = (const float*)d_in[wi + 3];
    const float* Wsg  = (const float*)d_in[wi + 4];
    const float* bsg  = (const float*)d_in[wi + 5];
    float* out = (float*)d_out;

    int n = in_sizes[0] / 64;
    int G = in_sizes[1] / 128;

    const size_t smem = (size_t)(4096 + CAP * 64 + 6 * 64) * sizeof(float); // 99840 B
    cudaFuncSetAttribute(group_kernel, cudaFuncAttributeMaxDynamicSharedMemorySize,
                         (int)smem);

    init_kernel<<<(G + 255) / 256, 256>>>(G);
    musig_kernel<<<(G + 3) / 4, 256>>>(feat, Wmu, bmu, Wsg, bsg, G);
    hist_kernel<<<(n + 255) / 256, 256>>>(seg, n);
    scan_kernel<<<1, 1024>>>(G);
    scatter_kernel<<<(n + 255) / 256, 256>>>(seg, n);
    group_kernel<<<G, 256, smem>>>(x, Wfc, bfc, out);
}